// round 3
// baseline (speedup 1.0000x reference)
#include <cuda_runtime.h>
#include <cuda_bf16.h>

// Problem constants
#define BB 8
#define SS 4096
#define DD 1024
#define AA 3
#define CC 2
#define KK 64
#define MARGIN 5.0f
#define ROWS (BB * SS)          // 32768
#define FLATN (SS * AA)         // 12288 per batch

// Output layout (float32):
//   [0]                      loss
//   [1 .. 1+98304)           predict_label (B,S,A)
//   [98305 .. 98305+1536)    total_idx (B*K, 3)
//   [99841 .. 99841+512)     candidate_label (B*K)
#define OFF_PRED 1
#define OFF_TI   (1 + ROWS * AA)            // 98305
#define OFF_CAND (OFF_TI + BB * KK * 3)     // 99841

// Scratch (static device globals -- no allocations allowed)
__device__ float g_part[ROWS * 4 * 6];      // per-warp GEMM partials (3 MB)
__device__ float g_logits[ROWS * 6];        // full logits (768 KB)
__device__ float g_loss[BB];                // per-batch loss partial sums

// ---------------------------------------------------------------------------
// Kernel 1: X(32768x1024) @ W(1024x6) partial sums.
// Block = 128 threads (4 warps). Thread t owns d in {4t..4t+3} U {512+4t..512+4t+3}
// with the corresponding 48 W values held in registers. Per row: 48 FMAs/thread,
// warp shfl-xor reduce of 6 accumulators, lanes 0..5 store the warp partial.
// Deterministic (no atomics).
// ---------------------------------------------------------------------------
#define RPB 32   // rows per block; grid = 32768/32 = 1024
__global__ void __launch_bounds__(128, 6)
k_gemm(const float* __restrict__ X, const float* __restrict__ W)
{
    const int t    = threadIdx.x;        // 0..127
    const int warp = t >> 5;
    const int lane = t & 31;

    // wA[j*6+k] = W[4t + j][k],  wB[j*6+k] = W[512 + 4t + j][k]
    float wA[24], wB[24];
#pragma unroll
    for (int i = 0; i < 24; i++) {
        wA[i] = W[t * 24 + i];
        wB[i] = W[(512 + 4 * t) * 6 + i];
    }

    const int row0 = blockIdx.x * RPB;
    const float4* __restrict__ X4 = reinterpret_cast<const float4*>(X);

#pragma unroll 2
    for (int r = 0; r < RPB; r++) {
        const int row = row0 + r;
        const float4 xa = __ldg(&X4[(size_t)row * 256 + t]);         // d = 4t..4t+3
        const float4 xb = __ldg(&X4[(size_t)row * 256 + 128 + t]);   // d = 512+4t..

        float xav[4] = {xa.x, xa.y, xa.z, xa.w};
        float xbv[4] = {xb.x, xb.y, xb.z, xb.w};

        float acc[6];
#pragma unroll
        for (int k = 0; k < 6; k++) acc[k] = 0.0f;
#pragma unroll
        for (int j = 0; j < 4; j++) {
#pragma unroll
            for (int k = 0; k < 6; k++) {
                acc[k] = fmaf(xav[j], wA[j * 6 + k], acc[k]);
                acc[k] = fmaf(xbv[j], wB[j * 6 + k], acc[k]);
            }
        }

#pragma unroll
        for (int off = 16; off > 0; off >>= 1) {
#pragma unroll
            for (int k = 0; k < 6; k++)
                acc[k] += __shfl_xor_sync(0xffffffffu, acc[k], off);
        }

        if (lane < 6)
            g_part[((size_t)row * 4 + warp) * 6 + lane] = acc[lane];
    }
}

// ---------------------------------------------------------------------------
// Kernel 2: combine 4 warp partials + bias -> logits; compute predict_label.
// argmax over C=2 with first-max tie-break => label 1 iff p1 > p0 (strict).
// ---------------------------------------------------------------------------
__global__ void k_final(const float* __restrict__ bias, float* __restrict__ out)
{
    const int row = blockIdx.x * blockDim.x + threadIdx.x;
    if (row >= ROWS) return;

    float l[6];
#pragma unroll
    for (int k = 0; k < 6; k++) l[k] = __ldg(&bias[k]);

    const float* p = g_part + (size_t)row * 24;
#pragma unroll
    for (int w = 0; w < 4; w++)
#pragma unroll
        for (int k = 0; k < 6; k++)
            l[k] += p[w * 6 + k];

#pragma unroll
    for (int k = 0; k < 6; k++) g_logits[(size_t)row * 6 + k] = l[k];

#pragma unroll
    for (int a = 0; a < AA; a++)
        out[OFF_PRED + (size_t)row * AA + a] = (l[2 * a + 1] > l[2 * a]) ? 1.0f : 0.0f;
}

// ---------------------------------------------------------------------------
// Kernel 3: per-batch selection. Positives are forced to exactly 2.0 (> any
// sigmoid < 1) and stable top_k => select the first 64 flat positions
// (ascending) with label==1. Labels are INT32 (jax x64 disabled: astype(int64)
// is a silent no-op). Emit total_idx, candidate_label, per-batch loss partial.
// One block per batch, 256 threads.
// ---------------------------------------------------------------------------
__global__ void k_select(const int* __restrict__ labels, float* __restrict__ out)
{
    const int b    = blockIdx.x;
    const int tid  = threadIdx.x;
    const int lane = tid & 31;
    const int warp = tid >> 5;

    __shared__ int   s_idx[KK];
    __shared__ int   s_cnt[8];
    __shared__ float s_red[8];

    const int* lab = labels + (size_t)b * FLATN;

    int found = 0;  // uniform across all threads
    for (int base = 0; base < FLATN && found < KK; base += 256) {
        const int t = base + tid;                       // FLATN % 256 == 0
        const int v = (lab[t] == 1);
        const unsigned m = __ballot_sync(0xffffffffu, v);
        if (lane == 0) s_cnt[warp] = __popc(m);
        __syncthreads();

        int wbase = found;
        for (int w = 0; w < warp; w++) wbase += s_cnt[w];
        const int g = wbase + __popc(m & ((1u << lane) - 1u));
        if (v && g < KK) s_idx[g] = t;

        int tot = 0;
#pragma unroll
        for (int w = 0; w < 8; w++) tot += s_cnt[w];
        found += tot;
        __syncthreads();
    }

    float term = 0.0f;
    if (tid < KK) {
        const int flat = s_idx[tid];
        const int s = flat / AA;
        const int a = flat - s * AA;
        const int row = b * SS + s;
        const size_t samp = (size_t)b * KK + tid;

        out[OFF_TI + samp * 3 + 0] = (float)b;
        out[OFF_TI + samp * 3 + 1] = (float)s;
        out[OFF_TI + samp * 3 + 2] = (float)a;

        const float p0 = g_logits[(size_t)row * 6 + 2 * a];
        const float p1 = g_logits[(size_t)row * 6 + 2 * a + 1];
        out[OFF_CAND + samp] = (p1 > p0) ? 1.0f : 0.0f;

        // selected positions always have label 1 => y = 1
        term = fmaxf(0.0f, MARGIN - p1 + p0) * (1.0f / CC);
    }

    // block reduce of loss terms (deterministic)
#pragma unroll
    for (int off = 16; off > 0; off >>= 1)
        term += __shfl_xor_sync(0xffffffffu, term, off);
    if (lane == 0) s_red[warp] = term;
    __syncthreads();
    if (tid == 0) {
        float s = 0.0f;
#pragma unroll
        for (int w = 0; w < 8; w++) s += s_red[w];
        g_loss[b] = s;
    }
}

// ---------------------------------------------------------------------------
// Kernel 4: final loss scalar = mean over B*K samples.
// ---------------------------------------------------------------------------
__global__ void k_loss(float* __restrict__ out)
{
    if (threadIdx.x == 0) {
        float s = 0.0f;
#pragma unroll
        for (int b = 0; b < BB; b++) s += g_loss[b];
        out[0] = s / (float)(BB * KK);
    }
}

// ---------------------------------------------------------------------------
extern "C" void kernel_launch(void* const* d_in, const int* in_sizes, int n_in,
                              void* d_out, int out_size)
{
    const float* X      = (const float*)d_in[0];    // (B,S,D) f32
    const float* W      = (const float*)d_in[1];    // (D, A*C) f32
    const float* bias   = (const float*)d_in[2];    // (A*C,) f32
    const int*   labels = (const int*)d_in[3];      // (B,S,A) int32 (jax x64 off)
    float*       out    = (float*)d_out;

    k_gemm  <<<ROWS / RPB, 128>>>(X, W);
    k_final <<<(ROWS + 255) / 256, 256>>>(bias, out);
    k_select<<<BB, 256>>>(labels, out);
    k_loss  <<<1, 32>>>(out);
}

// round 4
// speedup vs baseline: 1.1706x; 1.1706x over previous
#include <cuda_runtime.h>
#include <cuda_bf16.h>

// Problem constants
#define BB 8
#define SS 4096
#define DD 1024
#define AA 3
#define CC 2
#define KK 64
#define MARGIN 5.0f
#define ROWS (BB * SS)          // 32768
#define FLATN (SS * AA)         // 12288 per batch

// Output layout (float32):
//   [0] loss | [1..) predict_label (B,S,A) | total_idx (B*K,3) | candidate_label (B*K)
#define OFF_PRED 1
#define OFF_TI   (1 + ROWS * AA)            // 98305
#define OFF_CAND (OFF_TI + BB * KK * 3)     // 99841

// Scratch (static device globals -- no allocations allowed)
__device__ float g_logits[ROWS * 6];        // full logits (768 KB)
__device__ float g_loss[BB];                // per-batch loss partials
__device__ int   g_ctr;                     // zero-initialized; reset each launch

// ---------------------------------------------------------------------------
// Kernel 1 (fused): X(32768x1024) @ W(1024x6) + bias -> logits + predict_label.
// Grid = 888 = 148 SMs x 6 blocks  => exactly one wave (no quantization tail).
// Blocks 0..799 take 37 rows, 800..887 take 36 (32768 = 800*37 + 88*36).
// Block = 128 threads (4 warps). Thread t owns d in {4t..4t+3} U {512+4t..4t+3}
// (48 W coefficients in registers). Per row: 48 FMAs/thread, 18-SHFL reduced
// butterfly (6 accs -> 3 live per half-warp), per-warp partials to smem,
// cross-warp combine once at the end. Deterministic (no float atomics).
// ---------------------------------------------------------------------------
#define NBLK 888
#define MAXR 37

__global__ void __launch_bounds__(128, 6)
k_gemm(const float* __restrict__ X, const float* __restrict__ W,
       const float* __restrict__ bias, float* __restrict__ out)
{
    __shared__ float sPart[MAXR * 24];   // [row][warp*6 + k]
    __shared__ float sFin[MAXR * 6];

    const int t    = threadIdx.x;        // 0..127
    const int warp = t >> 5;
    const int lane = t & 31;
    const int bid  = blockIdx.x;

    const int start = bid * 36 + min(bid, 800);
    const int nrows = 36 + (bid < 800 ? 1 : 0);

    // wA[j*6+k] = W[4t + j][k],  wB[j*6+k] = W[512 + 4t + j][k]
    float wA[24], wB[24];
#pragma unroll
    for (int i = 0; i < 24; i++) {
        wA[i] = W[t * 24 + i];
        wB[i] = W[(512 + 4 * t) * 6 + i];
    }

    const float4* __restrict__ X4 = reinterpret_cast<const float4*>(X);

#pragma unroll 2
    for (int r = 0; r < nrows; r++) {
        const int row = start + r;
        const float4 xa = __ldg(&X4[(size_t)row * 256 + t]);         // d = 4t..4t+3
        const float4 xb = __ldg(&X4[(size_t)row * 256 + 128 + t]);   // d = 512+4t..

        const float xav[4] = {xa.x, xa.y, xa.z, xa.w};
        const float xbv[4] = {xb.x, xb.y, xb.z, xb.w};

        float acc[6];
#pragma unroll
        for (int k = 0; k < 6; k++) acc[k] = 0.0f;
#pragma unroll
        for (int j = 0; j < 4; j++)
#pragma unroll
            for (int k = 0; k < 6; k++) {
                acc[k] = fmaf(xav[j], wA[j * 6 + k], acc[k]);
                acc[k] = fmaf(xbv[j], wB[j * 6 + k], acc[k]);
            }

        // Stage 1 (offset 16): fold to 3 live values per half-warp.
        float o[6];
#pragma unroll
        for (int k = 0; k < 6; k++) o[k] = __shfl_xor_sync(0xffffffffu, acc[k], 16);
        float r0, r1, r2;
        if (lane < 16) { r0 = acc[0] + o[0]; r1 = acc[1] + o[1]; r2 = acc[2] + o[2]; }
        else           { r0 = acc[3] + o[3]; r1 = acc[4] + o[4]; r2 = acc[5] + o[5]; }

        // Stages 8/4/2/1 stay within each half (xor < 16).
#pragma unroll
        for (int off = 8; off > 0; off >>= 1) {
            r0 += __shfl_xor_sync(0xffffffffu, r0, off);
            r1 += __shfl_xor_sync(0xffffffffu, r1, off);
            r2 += __shfl_xor_sync(0xffffffffu, r2, off);
        }
        // lane 0: full sums of k=0,1,2; lane 16: full sums of k=3,4,5.
        if (lane == 0) {
            sPart[r * 24 + warp * 6 + 0] = r0;
            sPart[r * 24 + warp * 6 + 1] = r1;
            sPart[r * 24 + warp * 6 + 2] = r2;
        }
        if (lane == 16) {
            sPart[r * 24 + warp * 6 + 3] = r0;
            sPart[r * 24 + warp * 6 + 4] = r1;
            sPart[r * 24 + warp * 6 + 5] = r2;
        }
    }
    __syncthreads();

    // Cross-warp combine + bias; write logits (coalesced) and keep in smem.
    for (int v = t; v < nrows * 6; v += 128) {
        const int row = v / 6;
        const int k   = v - row * 6;
        float s = __ldg(&bias[k]);
#pragma unroll
        for (int w = 0; w < 4; w++) s += sPart[row * 24 + w * 6 + k];
        g_logits[(size_t)(start + row) * 6 + k] = s;
        sFin[v] = s;
    }
    __syncthreads();

    // predict_label: argmax over C=2, first-max tie-break => 1 iff p1 > p0.
    for (int u = t; u < nrows * 3; u += 128) {
        const int row = u / 3;
        const int a   = u - row * 3;
        out[OFF_PRED + (size_t)(start + row) * 3 + a] =
            (sFin[row * 6 + 2 * a + 1] > sFin[row * 6 + 2 * a]) ? 1.0f : 0.0f;
    }
}

// ---------------------------------------------------------------------------
// Kernel 2 (fused select + loss): positives are forced to exactly 2.0 (> any
// sigmoid < 1) and stable top_k => select the first 64 flat positions
// (ascending) with label==1. Labels are INT32 (jax x64 off). Emits total_idx,
// candidate_label, per-batch loss; the LAST block finalizes the loss scalar
// (single thread, fixed summation order => deterministic).
// One block per batch, 256 threads.
// ---------------------------------------------------------------------------
__global__ void k_select(const int* __restrict__ labels, float* __restrict__ out)
{
    const int b    = blockIdx.x;
    const int tid  = threadIdx.x;
    const int lane = tid & 31;
    const int warp = tid >> 5;

    __shared__ int   s_idx[KK];
    __shared__ int   s_cnt[8];
    __shared__ float s_red[8];

    const int* lab = labels + (size_t)b * FLATN;

    int found = 0;  // uniform across all threads
    for (int base = 0; base < FLATN && found < KK; base += 256) {
        const int t = base + tid;                       // FLATN % 256 == 0
        const int v = (lab[t] == 1);
        const unsigned m = __ballot_sync(0xffffffffu, v);
        if (lane == 0) s_cnt[warp] = __popc(m);
        __syncthreads();

        int wbase = found;
        for (int w = 0; w < warp; w++) wbase += s_cnt[w];
        const int g = wbase + __popc(m & ((1u << lane) - 1u));
        if (v && g < KK) s_idx[g] = t;

        int tot = 0;
#pragma unroll
        for (int w = 0; w < 8; w++) tot += s_cnt[w];
        found += tot;
        __syncthreads();
    }

    float term = 0.0f;
    if (tid < KK) {
        const int flat = s_idx[tid];
        const int s = flat / AA;
        const int a = flat - s * AA;
        const int row = b * SS + s;
        const size_t samp = (size_t)b * KK + tid;

        out[OFF_TI + samp * 3 + 0] = (float)b;
        out[OFF_TI + samp * 3 + 1] = (float)s;
        out[OFF_TI + samp * 3 + 2] = (float)a;

        const float p0 = g_logits[(size_t)row * 6 + 2 * a];
        const float p1 = g_logits[(size_t)row * 6 + 2 * a + 1];
        out[OFF_CAND + samp] = (p1 > p0) ? 1.0f : 0.0f;

        // selected positions always have label 1 => y = 1
        term = fmaxf(0.0f, MARGIN - p1 + p0) * (1.0f / CC);
    }

    // block reduce of loss terms (deterministic)
#pragma unroll
    for (int off = 16; off > 0; off >>= 1)
        term += __shfl_xor_sync(0xffffffffu, term, off);
    if (lane == 0) s_red[warp] = term;
    __syncthreads();

    if (tid == 0) {
        float s = 0.0f;
#pragma unroll
        for (int w = 0; w < 8; w++) s += s_red[w];
        g_loss[b] = s;
        __threadfence();
        if (atomicAdd(&g_ctr, 1) == BB - 1) {
            volatile float* gl = g_loss;
            float tot = 0.0f;
#pragma unroll
            for (int b2 = 0; b2 < BB; b2++) tot += gl[b2];
            out[0] = tot / (float)(BB * KK);
            g_ctr = 0;      // ready for next graph replay
        }
    }
}

// ---------------------------------------------------------------------------
extern "C" void kernel_launch(void* const* d_in, const int* in_sizes, int n_in,
                              void* d_out, int out_size)
{
    const float* X      = (const float*)d_in[0];    // (B,S,D) f32
    const float* W      = (const float*)d_in[1];    // (D, A*C) f32
    const float* bias   = (const float*)d_in[2];    // (A*C,) f32
    const int*   labels = (const int*)d_in[3];      // (B,S,A) int32 (jax x64 off)
    float*       out    = (float*)d_out;

    k_gemm  <<<NBLK, 128>>>(X, W, bias, out);
    k_select<<<BB, 256>>>(labels, out);
}